// round 2
// baseline (speedup 1.0000x reference)
#include <cuda_runtime.h>
#include <cstdint>

#define W    1280
#define H    720
#define BB   8
#define NROWS (BB * H)        // 5760 rows
#define THREADS 160           // 5 warps: one per accumulation array
#define CHUNK 43              // per-lane input chunk; 43 > 42-wide scatter window
#define EPSV 1e-6f
// log2(1.414), double-accurate
#define K_LOG2 0.49978215486f

__device__ int g_minbits;

__global__ void init_min_kernel() {
    g_minbits = 0x7F800000;   // +inf
}

__global__ void min_kernel(const float4* __restrict__ disp4, int n4) {
    int idx = blockIdx.x * blockDim.x + threadIdx.x;
    int stride = gridDim.x * blockDim.x;
    float m = 1e30f;
    for (int i = idx; i < n4; i += stride) {
        float4 v = disp4[i];
        m = fminf(m, fminf(fminf(v.x, v.y), fminf(v.z, v.w)));
    }
    #pragma unroll
    for (int o = 16; o; o >>= 1)
        m = fminf(m, __shfl_xor_sync(0xFFFFFFFFu, m, o));
    __shared__ float sm[8];
    int lane = threadIdx.x & 31, wid = threadIdx.x >> 5;
    if (lane == 0) sm[wid] = m;
    __syncthreads();
    if (wid == 0) {
        m = (lane < (int)(blockDim.x >> 5)) ? sm[lane] : 1e30f;
        #pragma unroll
        for (int o = 4; o; o >>= 1)
            m = fminf(m, __shfl_xor_sync(0xFFFFFFFFu, m, o));
        if (lane == 0)
            atomicMin(&g_minbits, __float_as_int(m));  // all disp >= 0: bit-compare valid
    }
}

__global__ __launch_bounds__(THREADS, 4)
void warp_splat_kernel(const float* __restrict__ im,
                       const float* __restrict__ disp,
                       float* __restrict__ res,
                       float* __restrict__ occ) {
    __shared__ float s_disp[W];
    __shared__ float s_im[3][W];
    __shared__ float s_acc[5][W];   // r, g, b, mask, occ

    const int row = blockIdx.x;            // 0..5759
    const int b = row / H;
    const int y = row - b * H;
    const float* drow  = disp + (size_t)row * W;
    const float* imrow = im + ((size_t)b * 3 * H + y) * W;   // + c*H*W per channel

    const int t = threadIdx.x;

    // ---- stage inputs (coalesced float4) + zero accumulators ----
    {
        const float4* d4 = (const float4*)drow;
        float4* sd4 = (float4*)s_disp;
        for (int i = t; i < W / 4; i += THREADS) sd4[i] = d4[i];
        #pragma unroll
        for (int c = 0; c < 3; ++c) {
            const float4* i4 = (const float4*)(imrow + (size_t)c * H * W);
            float4* si4 = (float4*)s_im[c];
            for (int i = t; i < W / 4; i += THREADS) si4[i] = i4[i];
        }
        const float4 z = make_float4(0.f, 0.f, 0.f, 0.f);
        float4* sa4 = (float4*)&s_acc[0][0];
        for (int i = t; i < 5 * W / 4; i += THREADS) sa4[i] = z;
    }
    __syncthreads();

    const float dmin = __int_as_float(g_minbits);

    const int lane = t & 31;
    const int warp = t >> 5;          // 0..4 -> which array this warp owns
    const int base = lane * CHUNK;    // lanes 0..29 cover the row; 30,31 idle
    float* acc = s_acc[warp];

    // Race-free lockstep scatter: at step s, lane l touches columns in
    // [43l+s-40, 43l+s+1]; disjoint across lanes. __syncwarp orders steps.
    #pragma unroll 1
    for (int s = 0; s < CHUNK; ++s) {
        const int i = base + s;
        if (lane < 30 && i < W) {
            const float d   = s_disp[i];
            const float x   = (float)i - d;
            const float x0f = floorf(x);
            const float f   = x - x0f;
            const int   x0  = (int)x0f;
            float a0, a1;
            if (warp == 4) {                    // occ: splat of ones
                a0 = 1.0f - f; a1 = f;
            } else {
                const float e = K_LOG2 * (d - dmin);
                float w;
                asm("ex2.approx.f32 %0, %1;" : "=f"(w) : "f"(e));
                const float wf = w * f;
                const float w0 = w - wf;
                if (warp == 3) {                // mask: splat of w
                    a0 = w0; a1 = wf;
                } else {                        // r/g/b: splat of v*w
                    const float v = s_im[warp][i];
                    a0 = v * w0; a1 = v * wf;
                }
            }
            if ((unsigned)x0 < (unsigned)W) acc[x0] += a0;
            const int x1 = x0 + 1;
            if ((unsigned)x1 < (unsigned)W) acc[x1] += a1;
        }
        __syncwarp();
    }
    __syncthreads();

    // ---- writeback: res = acc/max(mask,eps), occ = 1 - clip(occacc,0,1) ----
    float* resrow = res + ((size_t)b * 3 * H + y) * W;
    float* occrow = occ + (size_t)row * W;
    for (int c = t; c < W; c += THREADS) {
        const float m = fmaxf(s_acc[3][c], EPSV);
        float inv;
        asm("rcp.approx.f32 %0, %1;" : "=f"(inv) : "f"(m));
        resrow[c]             = s_acc[0][c] * inv;
        resrow[(size_t)H * W + c]     = s_acc[1][c] * inv;
        resrow[(size_t)2 * H * W + c] = s_acc[2][c] * inv;
        const float o = s_acc[4][c];
        occrow[c] = 1.0f - fminf(fmaxf(o, 0.0f), 1.0f);
    }
}

extern "C" void kernel_launch(void* const* d_in, const int* in_sizes, int n_in,
                              void* d_out, int out_size) {
    const float* im   = (const float*)d_in[0];   // [8,3,720,1280]
    const float* disp = (const float*)d_in[1];   // [8,1,720,1280]
    float* res = (float*)d_out;                              // [8,3,720,1280]
    float* occ = (float*)d_out + (size_t)BB * 3 * H * W;     // [8,1,720,1280]

    init_min_kernel<<<1, 1>>>();
    min_kernel<<<1024, 256>>>((const float4*)disp, BB * H * W / 4);
    warp_splat_kernel<<<NROWS, THREADS>>>(im, disp, res, occ);
}